// round 15
// baseline (speedup 1.0000x reference)
#include <cuda_runtime.h>
#include <cuda_fp16.h>
#include <cstdint>

// Problem constants
#define BB 4
#define SS 4096
#define DF 1024
#define HH 16
#define HD 64
#define SK 1024          // SS / STRIDE
#define STRIDE 4
#define BQ 128           // q rows per CTA
#define BK 64            // k cols per block
#define NBLK 16
#define NT 256
#define NQB 32           // q-blocks per (b,h)

// fp16 fragment-major scratch (packed half2 in uint) — layouts verified R14
__device__ uint2 g_kh[BB * HH * NBLK * 1024];
__device__ uint2 g_vh[BB * HH * NBLK * 1024];
__device__ uint4 g_qh[BB * HH * NQB * 1024];

#define STGB 8192                   // bytes per K/V stage
#define WPAD 68                     // floats per w-buffer row (272B, 16B-aligned)
#define WBUFB (BQ * WPAD * 4)       // 34816 bytes per w buffer
#define SM_W0 32768
#define SM_W1 (SM_W0 + WBUFB)
#define SM_TOTAL (SM_W1 + WBUFB)    // 102400 bytes

__device__ __forceinline__ uint32_t smem_u32(const void* p) {
    uint32_t a;
    asm("{ .reg .u64 t; cvta.to.shared.u64 t, %1; cvt.u32.u64 %0, t; }" : "=r"(a) : "l"(p));
    return a;
}
#define CP_ASYNC16(sa, gp) \
    asm volatile("cp.async.cg.shared.global [%0], [%1], 16;" :: "r"(sa), "l"(gp) : "memory")
#define CP_COMMIT() asm volatile("cp.async.commit_group;" ::: "memory")
#define CP_WAIT(N)  asm volatile("cp.async.wait_group %0;" :: "n"(N) : "memory")

// SMEM -> GMEM bulk copy (async proxy; leaves the LSU/L1 store path)
#define BULK_S2G(gp, sa, bytes) \
    asm volatile("cp.async.bulk.global.shared::cta.bulk_group [%0], [%1], %2;" \
                 :: "l"(gp), "r"(sa), "r"(bytes) : "memory")
#define BULK_COMMIT()      asm volatile("cp.async.bulk.commit_group;" ::: "memory")
#define BULK_WAIT_READ1()  asm volatile("cp.async.bulk.wait_group.read 1;" ::: "memory")
#define BULK_WAIT_ALL()    asm volatile("cp.async.bulk.wait_group 0;" ::: "memory")
#define FENCE_PROXY_ASYNC() asm volatile("fence.proxy.async.shared::cta;" ::: "memory")

// C += A * B, m16n8k16 fp16 inputs, fp32 accumulate
__device__ __forceinline__ void mma_f16(float c[4], uint32_t a0, uint32_t a1,
                                        uint32_t a2, uint32_t a3,
                                        uint32_t b0, uint32_t b1) {
    asm volatile(
        "mma.sync.aligned.m16n8k16.row.col.f32.f16.f16.f32 "
        "{%0,%1,%2,%3}, {%4,%5,%6,%7}, {%8,%9}, {%0,%1,%2,%3};"
        : "+f"(c[0]), "+f"(c[1]), "+f"(c[2]), "+f"(c[3])
        : "r"(a0), "r"(a1), "r"(a2), "r"(a3), "r"(b0), "r"(b1));
}
__device__ __forceinline__ uint32_t packh2(float a, float b) {
    __half2 h = __floats2half2_rn(a, b);
    return *reinterpret_cast<uint32_t*>(&h);
}
__device__ __forceinline__ float ex2f(float x) {
    float y;
    asm("ex2.approx.f32 %0, %1;" : "=f"(y) : "f"(x));
    return y;
}

// ---- pre-kernels (verbatim from R14; verified) ----
__global__ __launch_bounds__(NT)
void shuffle_kvh_kernel(const float* __restrict__ gk, const float* __restrict__ gv)
{
    int id = blockIdx.x * NT + threadIdx.x;
    int lane = id & 31, t = (id >> 5) & 7, chunk = (id >> 8) & 3;
    int kblk = (id >> 10) & 15, bh = id >> 14;
    int gid = lane >> 2, gc = lane & 3;
    int bi = bh >> 4, hc = (bh & 15) * HD;
    size_t o = (size_t)(id >> 10) * 1024 + (chunk * 8 + t) * 32 + lane;
    {
        int srow = kblk * 64 + t * 8 + gid;
        const float* src = gk + ((size_t)bi * SS + (size_t)srow * STRIDE) * DF
                         + hc + chunk * 16 + 2 * gc;
        g_kh[o] = make_uint2(packh2(src[0], src[1]), packh2(src[8], src[9]));
    }
    {
        int key0 = kblk * 64 + chunk * 16 + 2 * gc;
        const float* src = gv + ((size_t)bi * SS + (size_t)key0 * STRIDE) * DF
                         + hc + t * 8 + gid;
        const size_t R = (size_t)STRIDE * DF;
        g_vh[o] = make_uint2(packh2(src[0], src[R]),
                             packh2(src[8 * R], src[9 * R]));
    }
}
__global__ __launch_bounds__(NT)
void shuffle_qh_kernel(const float* __restrict__ gq)
{
    const float SCL = 0.125f * 1.44269504088896341f;
    int id = blockIdx.x * NT + threadIdx.x;
    int lane = id & 31, warp = (id >> 5) & 7, chunk = (id >> 8) & 3;
    int qblk = (id >> 10) & 31, bh = id >> 15;
    int gid = lane >> 2, gc = lane & 3;
    int r = qblk * BQ + warp * 16 + gid;
    const float* src = gq + ((size_t)(bh >> 4) * SS + r) * DF
                     + (bh & 15) * HD + chunk * 16 + 2 * gc;
    const size_t R8 = (size_t)8 * DF;
    uint32_t a0 = packh2(src[0] * SCL,      src[1] * SCL);
    uint32_t a1 = packh2(src[R8] * SCL,     src[R8 + 1] * SCL);
    uint32_t a2 = packh2(src[8] * SCL,      src[9] * SCL);
    uint32_t a3 = packh2(src[R8 + 8] * SCL, src[R8 + 9] * SCL);
    g_qh[(size_t)(id >> 10) * 1024 + (chunk * 8 + warp) * 32 + lane] =
        make_uint4(a0, a1, a2, a3);
}

__global__ __launch_bounds__(NT, 2)
void attn_mma_kernel(float* __restrict__ out_a, float* __restrict__ out_w)
{
    extern __shared__ char sm[];
    const uint32_t smb = smem_u32(sm);

    const int tid = threadIdx.x, lane = tid & 31, warp = tid >> 5;
    const int gid = lane >> 2, gc = lane & 3;
    const int b = blockIdx.z, hh = blockIdx.y, qblk = blockIdx.x;
    const int bh = b * HH + hh;

    const uint2* kh = g_kh + (size_t)bh * NBLK * 1024;
    const uint2* vh = g_vh + (size_t)bh * NBLK * 1024;
    const uint4* qh = g_qh + ((size_t)bh * NQB + qblk) * 1024;

    // ---- pass1 pre-issue: K blocks 0..2 into ring stages 0..2 ----
    #pragma unroll
    for (int p = 0; p < 3; p++) {
        const char* src = (const char*)(kh + p * 1024);
        #pragma unroll
        for (int i = 0; i < 2; i++) {
            int cix = tid + i * NT;
            CP_ASYNC16(smb + p * STGB + cix * 16, src + cix * 16);
        }
        CP_COMMIT();
    }

    // ---- Q fragments -> registers ----
    uint4 Qh[4];
    #pragma unroll
    for (int j = 0; j < 4; j++)
        Qh[j] = qh[(j * 8 + warp) * 32 + lane];

    float rs0 = 0.f, rs1 = 0.f;

    // ================= PASS 1: row sums (K ring, 4 stages) =================
    for (int blk = 0; blk < NBLK; blk++) {
        if      (blk < NBLK - 2)  CP_WAIT(2);
        else if (blk == NBLK - 2) CP_WAIT(1);
        else                      CP_WAIT(0);
        __syncthreads();

        if (blk + 3 < NBLK) {
            const char* src = (const char*)(kh + (blk + 3) * 1024);
            const uint32_t st = smb + ((blk + 3) & 3) * STGB;
            #pragma unroll
            for (int i = 0; i < 2; i++) {
                int cix = tid + i * NT;
                CP_ASYNC16(st + cix * 16, src + cix * 16);
            }
            CP_COMMIT();
        }

        const uint2* kb = (const uint2*)(sm + (blk & 3) * STGB);

        float S[8][4];
        #pragma unroll
        for (int t = 0; t < 8; t++) {
            S[t][0] = 0.f; S[t][1] = 0.f; S[t][2] = 0.f; S[t][3] = 0.f;
        }
        #pragma unroll
        for (int j = 0; j < 4; j++) {
            #pragma unroll
            for (int t = 0; t < 8; t++) {
                uint2 bk = kb[(j * 8 + t) * 32 + lane];
                mma_f16(S[t], Qh[j].x, Qh[j].y, Qh[j].z, Qh[j].w, bk.x, bk.y);
            }
        }
        #pragma unroll
        for (int t = 0; t < 8; t++) {
            rs0 += ex2f(S[t][0]) + ex2f(S[t][1]);
            rs1 += ex2f(S[t][2]) + ex2f(S[t][3]);
        }
    }

    // quad reduce (warp-local)
    rs0 += __shfl_xor_sync(0xFFFFFFFFu, rs0, 1);
    rs0 += __shfl_xor_sync(0xFFFFFFFFu, rs0, 2);
    rs1 += __shfl_xor_sync(0xFFFFFFFFu, rs1, 1);
    rs1 += __shfl_xor_sync(0xFFFFFFFFu, rs1, 2);
    const float inv0 = 1.0f / rs0, inv1 = 1.0f / rs1;

    // ---- pass2 pre-issue: K0 -> stage0, V0 -> stage2 ----
    {
        #pragma unroll
        for (int i = 0; i < 2; i++) {
            int cix = tid + i * NT;
            CP_ASYNC16(smb + cix * 16,            (const char*)kh + cix * 16);
            CP_ASYNC16(smb + 2 * STGB + cix * 16, (const char*)vh + cix * 16);
        }
        CP_COMMIT();
    }

    float Acc[8][4];
    #pragma unroll
    for (int t = 0; t < 8; t++) {
        Acc[t][0] = 0.f; Acc[t][1] = 0.f; Acc[t][2] = 0.f; Acc[t][3] = 0.f;
    }

    // w row base for this CTA's slab
    float* wslab = out_w + ((size_t)bh * SS + qblk * BQ) * SK;

    // ================= PASS 2: normalized w (smem-staged, bulk-stored) + PV ==
    for (int blk = 0; blk < NBLK; blk++) {
        CP_WAIT(0);
        if (tid < BQ) BULK_WAIT_READ1();   // w buffer (blk&1) reads done (blk-2's copy)
        __syncthreads();

        if (blk + 1 < NBLK) {
            const uint32_t ks_ = smb + ((blk + 1) & 1) * STGB;
            const uint32_t vs_ = ks_ + 2 * STGB;
            const char* ksrc = (const char*)(kh + (blk + 1) * 1024);
            const char* vsrc = (const char*)(vh + (blk + 1) * 1024);
            #pragma unroll
            for (int i = 0; i < 2; i++) {
                int cix = tid + i * NT;
                CP_ASYNC16(ks_ + cix * 16, ksrc + cix * 16);
                CP_ASYNC16(vs_ + cix * 16, vsrc + cix * 16);
            }
            CP_COMMIT();
        }

        const uint2* kb = (const uint2*)(sm + (blk & 1) * STGB);
        const uint2* vb = (const uint2*)(sm + (2 + (blk & 1)) * STGB);

        // ---- S = Q * K^T  (identical op order to pass 1 -> same bits) ----
        float S[8][4];
        #pragma unroll
        for (int t = 0; t < 8; t++) {
            S[t][0] = 0.f; S[t][1] = 0.f; S[t][2] = 0.f; S[t][3] = 0.f;
        }
        #pragma unroll
        for (int j = 0; j < 4; j++) {
            #pragma unroll
            for (int t = 0; t < 8; t++) {
                uint2 bk = kb[(j * 8 + t) * 32 + lane];
                mma_f16(S[t], Qh[j].x, Qh[j].y, Qh[j].z, Qh[j].w, bk.x, bk.y);
            }
        }

        // ---- normalized w -> smem buffer; P packed to fp16 a-frags ----
        float* wb = (float*)(sm + ((blk & 1) ? SM_W1 : SM_W0));
        float* wb0 = wb + (warp * 16 + gid) * WPAD;
        float* wb1 = wb0 + 8 * WPAD;
        uint32_t Ph[8][2];
        #pragma unroll
        for (int t = 0; t < 8; t++) {
            float p0 = ex2f(S[t][0]) * inv0, p1 = ex2f(S[t][1]) * inv0;
            float p2 = ex2f(S[t][2]) * inv1, p3 = ex2f(S[t][3]) * inv1;
            int col = t * 8 + 2 * gc;
            *(float2*)&wb0[col] = make_float2(p0, p1);
            *(float2*)&wb1[col] = make_float2(p2, p3);
            Ph[t][0] = packh2(p0, p1);
            Ph[t][1] = packh2(p2, p3);
        }

        // ---- Acc += P * V ----
        #pragma unroll
        for (int c = 0; c < 4; c++) {
            #pragma unroll
            for (int t = 0; t < 8; t++) {
                uint2 bv = vb[(c * 8 + t) * 32 + lane];
                mma_f16(Acc[t], Ph[2 * c][0], Ph[2 * c][1],
                        Ph[2 * c + 1][0], Ph[2 * c + 1][1], bv.x, bv.y);
            }
        }

        // ---- ship w tile: async bulk SMEM->GMEM, one row per thread ----
        __syncthreads();        // all warps' STS into wb complete
        FENCE_PROXY_ASYNC();    // make generic STS visible to async proxy
        if (tid < BQ) {
            uint32_t srow = smb + ((blk & 1) ? SM_W1 : SM_W0) + tid * (WPAD * 4);
            float* grow = wslab + (size_t)tid * SK + blk * BK;
            BULK_S2G(grow, srow, BK * 4);
            BULK_COMMIT();
        }
    }

    // ---- a: already normalized, warp-local store ----
    {
        float* ar0 = out_a + ((size_t)(b * SS + qblk * BQ + warp * 16 + gid)) * DF
                   + hh * HD;
        float* ar1 = ar0 + (size_t)8 * DF;
        #pragma unroll
        for (int t = 0; t < 8; t++) {
            int col = t * 8 + 2 * gc;
            *(float2*)&ar0[col] = make_float2(Acc[t][0], Acc[t][1]);
            *(float2*)&ar1[col] = make_float2(Acc[t][2], Acc[t][3]);
        }
    }

    // drain outstanding bulk stores before kernel end
    if (tid < BQ) BULK_WAIT_ALL();
}

extern "C" void kernel_launch(void* const* d_in, const int* in_sizes, int n_in,
                              void* d_out, int out_size)
{
    (void)in_sizes; (void)n_in; (void)out_size;
    const float* q = (const float*)d_in[0];
    const float* k = (const float*)d_in[1];
    const float* v = (const float*)d_in[2];

    float* out_a = (float*)d_out;
    float* out_w = out_a + (size_t)BB * SS * DF;  // w follows a

    shuffle_kvh_kernel<<<(BB * HH * NBLK * 1024) / NT, NT>>>(k, v);
    shuffle_qh_kernel<<<(BB * HH * NQB * 1024) / NT, NT>>>(q);

    cudaFuncSetAttribute(attn_mma_kernel,
                         cudaFuncAttributeMaxDynamicSharedMemorySize, SM_TOTAL);
    dim3 grid(NQB, HH, BB);   // (32, 16, 4) = 2048 CTAs
    attn_mma_kernel<<<grid, NT, SM_TOTAL>>>(out_a, out_w);
}